// round 2
// baseline (speedup 1.0000x reference)
#include <cuda_runtime.h>
#include <math.h>

#define BB 2
#define LL 225
#define DD 256
#define HH 4
#define HD 64
#define BH (BB*HH)
#define NROW (BB*LL)   // 450
#define RHO 0.1f

// ---------------- scratch (device globals; no allocation allowed) ----------
__device__ float g_q[BH*LL*HD];
__device__ float g_k[BH*LL*HD];
__device__ float g_v[BH*LL*HD];
__device__ float g_S[BH*LL*LL];
__device__ float g_A[BH*LL*LL];   // A, later overwritten with A_hat
__device__ float g_dis[BH*LL];
__device__ float g_T[BH*LL*LL];   // T = A_hat @ S
__device__ float g_P[BH*LL*LL];   // S_jump, then attn (softmaxed in place)
__device__ float g_O[BB*LL*DD];   // attn @ v, merged heads [b, l, h*64+dd]

// ---------------- K1: q,k,v projections (y = x @ W^T) ----------------------
// grid (24, 15), block (32,32). columns 0..767 = [Wq | Wk | Wv]
__global__ void qkv_kernel(const float* __restrict__ x,
                           const float* __restrict__ Wq,
                           const float* __restrict__ Wk,
                           const float* __restrict__ Wv) {
    __shared__ float xs[32][33];
    __shared__ float ws[32][33];
    int tx = threadIdx.x, ty = threadIdx.y;
    int r  = blockIdx.y * 32 + ty;
    int c0 = blockIdx.x * 32;
    const float* W = (c0 < 256) ? Wq : (c0 < 512) ? Wk : Wv;
    int o0 = c0 & 255;
    float acc = 0.f;
    for (int k0 = 0; k0 < 256; k0 += 32) {
        xs[ty][tx] = (r < NROW) ? x[r*256 + k0 + tx] : 0.f;
        ws[ty][tx] = W[(o0 + ty)*256 + k0 + tx];
        __syncthreads();
#pragma unroll
        for (int kk = 0; kk < 32; kk++) acc += xs[ty][kk] * ws[tx][kk];
        __syncthreads();
    }
    if (r < NROW) {
        int b = r / LL, l = r % LL;
        int c = c0 + tx;
        int which = c >> 8;
        int oo = c & 255;
        int h = oo >> 6, dd = oo & 63;
        float* dst = (which == 0) ? g_q : (which == 1) ? g_k : g_v;
        dst[((b*HH + h)*LL + l)*HD + dd] = acc;
    }
}

// ---------------- K2: S = q @ k^T per (b,h) --------------------------------
// grid (8, 8, 8), block (32,32)
__global__ void s_kernel() {
    __shared__ float qs[32][33], ks[32][33];
    int bh = blockIdx.z;
    int i0 = blockIdx.y * 32, j0 = blockIdx.x * 32;
    int tx = threadIdx.x, ty = threadIdx.y;
    const float* qb = g_q + bh*LL*HD;
    const float* kb = g_k + bh*LL*HD;
    float acc = 0.f;
    for (int k0 = 0; k0 < HD; k0 += 32) {
        int i = i0 + ty, j = j0 + ty;
        qs[ty][tx] = (i < LL) ? qb[i*HD + k0 + tx] : 0.f;
        ks[ty][tx] = (j < LL) ? kb[j*HD + k0 + tx] : 0.f;
        __syncthreads();
#pragma unroll
        for (int kk = 0; kk < 32; kk++) acc += qs[ty][kk] * ks[tx][kk];
        __syncthreads();
    }
    int i = i0 + ty, j = j0 + tx;
    if (i < LL && j < LL) g_S[bh*LL*LL + i*LL + j] = acc;
}

// ---------------- K3: adjacency A[i,k] = (1/L) sum_j g(S[i,j]S[k,j]/d) -----
// grid (8, 8, 8), block (16,16), 2x2 per thread
__global__ void a_kernel() {
    __shared__ float si[32][33], sk[32][33];
    int bh = blockIdx.z;
    int i0 = blockIdx.y * 32, k0 = blockIdx.x * 32;
    int tx = threadIdx.x, ty = threadIdx.y;
    const float* Sb = g_S + bh*LL*LL;
    float a00 = 0.f, a01 = 0.f, a10 = 0.f, a11 = 0.f;
    for (int j0 = 0; j0 < LL; j0 += 32) {
        int t = ty * 16 + tx;
#pragma unroll
        for (int e = 0; e < 4; e++) {
            int idx = t + e*256;
            int rr = idx >> 5, cc = idx & 31;
            int i = i0 + rr, j = j0 + cc, k = k0 + rr;
            si[rr][cc] = (i < LL && j < LL) ? Sb[i*LL + j] : 0.f;
            sk[rr][cc] = (k < LL && j < LL) ? Sb[k*LL + j] : 0.f;
        }
        __syncthreads();
#pragma unroll
        for (int jj = 0; jj < 32; jj++) {
            float ai0 = si[ty][jj],    ai1 = si[ty+16][jj];
            float bk0 = sk[tx][jj],    bk1 = sk[tx+16][jj];
            float u;
            u = ai0*bk0*(1.f/64.f); a00 += (u > RHO) ? u : 0.f;
            u = ai0*bk1*(1.f/64.f); a01 += (u > RHO) ? u : 0.f;
            u = ai1*bk0*(1.f/64.f); a10 += (u > RHO) ? u : 0.f;
            u = ai1*bk1*(1.f/64.f); a11 += (u > RHO) ? u : 0.f;
        }
        __syncthreads();
    }
    float* Ab = g_A + bh*LL*LL;
    const float invL = 1.f / (float)LL;
    int i, k;
    i = i0+ty;    k = k0+tx;    if (i<LL && k<LL) Ab[i*LL+k] = (i==k)?0.f:a00*invL;
    i = i0+ty;    k = k0+tx+16; if (i<LL && k<LL) Ab[i*LL+k] = (i==k)?0.f:a01*invL;
    i = i0+ty+16; k = k0+tx;    if (i<LL && k<LL) Ab[i*LL+k] = (i==k)?0.f:a10*invL;
    i = i0+ty+16; k = k0+tx+16; if (i<LL && k<LL) Ab[i*LL+k] = (i==k)?0.f:a11*invL;
}

// ---------------- K4a: degree -> d^{-1/2}, one warp per row ----------------
// grid 225, block 256 (8 warps)
__global__ void deg_kernel() {
    int w = threadIdx.x >> 5, lane = threadIdx.x & 31;
    int row = blockIdx.x * 8 + w;             // 0..1799
    if (row >= BH*LL) return;
    const float* Ar = g_A + row * LL;         // row = bh*L + i; A row base = bh*L*L + i*L
    float s = 0.f;
    for (int k = lane; k < LL; k += 32) s += Ar[k];
#pragma unroll
    for (int off = 16; off > 0; off >>= 1) s += __shfl_xor_sync(0xffffffffu, s, off);
    if (lane == 0) {
        float deg = fmaxf(1.f + s, 1e-6f);
        g_dis[row] = 1.f / sqrtf(deg);
    }
}

// ---------------- K4b: A_hat = dis[i]*(A + I)*dis[k] in place --------------
__global__ void ahat_kernel() {
    int idx = blockIdx.x * blockDim.x + threadIdx.x;
    if (idx >= BH*LL*LL) return;
    int bh = idx / (LL*LL);
    int rem = idx % (LL*LL);
    int i = rem / LL, k = rem % LL;
    float a = g_A[idx] + ((i == k) ? 1.f : 0.f);
    g_A[idx] = a * g_dis[bh*LL + i] * g_dis[bh*LL + k];
}

// ---------------- K5/K6: 225x225x225 GEMMs ---------------------------------
// MODE 0: T = A_hat @ S                 (scale 1)
// MODE 1: P = T @ A_hat^T / sqrt(64)    (scale 0.125)
// grid (8, 8, 8), block (16,16), 2x2 per thread
template<int MODE>
__global__ void gemm225_kernel() {
    __shared__ float as[32][33], bs[32][33];
    int bh = blockIdx.z;
    int i0 = blockIdx.y * 32, j0 = blockIdx.x * 32;
    int tx = threadIdx.x, ty = threadIdx.y;
    const float* Ab = ((MODE == 0) ? g_A : g_T) + bh*LL*LL;
    const float* Bb = ((MODE == 0) ? g_S : g_A) + bh*LL*LL;
    float*       Cb = ((MODE == 0) ? g_T : g_P) + bh*LL*LL;
    const float scale = (MODE == 0) ? 1.f : 0.125f;
    float c00 = 0.f, c01 = 0.f, c10 = 0.f, c11 = 0.f;
    for (int k0 = 0; k0 < LL; k0 += 32) {
        int t = ty * 16 + tx;
#pragma unroll
        for (int e = 0; e < 4; e++) {
            int idx = t + e*256;
            int rr = idx >> 5, cc = idx & 31;
            int i = i0 + rr, kc = k0 + cc;
            as[rr][cc] = (i < LL && kc < LL) ? Ab[i*LL + kc] : 0.f;
            if (MODE == 1) {
                // B^T: bs[kk][c] = B[j0+c][k0+kk]; load row j0+rr, cols k0+cc
                int j = j0 + rr;
                bs[cc][rr] = (j < LL && kc < LL) ? Bb[j*LL + kc] : 0.f;
            } else {
                int kr = k0 + rr, j = j0 + cc;
                bs[rr][cc] = (kr < LL && j < LL) ? Bb[kr*LL + j] : 0.f;
            }
        }
        __syncthreads();
#pragma unroll
        for (int kk = 0; kk < 32; kk++) {
            float a0 = as[ty][kk],    a1 = as[ty+16][kk];
            float b0 = bs[kk][tx],    b1 = bs[kk][tx+16];
            c00 += a0*b0; c01 += a0*b1; c10 += a1*b0; c11 += a1*b1;
        }
        __syncthreads();
    }
    int i, j;
    i = i0+ty;    j = j0+tx;    if (i<LL && j<LL) Cb[i*LL+j] = c00*scale;
    i = i0+ty;    j = j0+tx+16; if (i<LL && j<LL) Cb[i*LL+j] = c01*scale;
    i = i0+ty+16; j = j0+tx;    if (i<LL && j<LL) Cb[i*LL+j] = c10*scale;
    i = i0+ty+16; j = j0+tx+16; if (i<LL && j<LL) Cb[i*LL+j] = c11*scale;
}

// ---------------- K7: row softmax of P in place (one warp per row) ---------
__global__ void softmax_kernel() {
    int w = threadIdx.x >> 5, lane = threadIdx.x & 31;
    int row = blockIdx.x * 8 + w;
    if (row >= BH*LL) return;
    float* Pr = g_P + row * LL;
    float vals[8];
    float mx = -1e30f;
#pragma unroll
    for (int e = 0; e < 8; e++) {
        int j = lane + e*32;
        vals[e] = (j < LL) ? Pr[j] : -1e30f;
        mx = fmaxf(mx, vals[e]);
    }
#pragma unroll
    for (int off = 16; off > 0; off >>= 1) mx = fmaxf(mx, __shfl_xor_sync(0xffffffffu, mx, off));
    float s = 0.f;
#pragma unroll
    for (int e = 0; e < 8; e++) {
        int j = lane + e*32;
        vals[e] = expf(vals[e] - mx);
        if (j < LL) s += vals[e];
    }
#pragma unroll
    for (int off = 16; off > 0; off >>= 1) s += __shfl_xor_sync(0xffffffffu, s, off);
    float inv = 1.f / s;
#pragma unroll
    for (int e = 0; e < 8; e++) {
        int j = lane + e*32;
        if (j < LL) Pr[j] = vals[e] * inv;
    }
}

// ---------------- K8: O = attn @ v, merge heads ----------------------------
// grid (2, 8, 8), block (16,16), 2x2 per thread
__global__ void av_kernel() {
    __shared__ float ps[32][33], vs[32][33];
    int bh = blockIdx.z;
    int i0 = blockIdx.y * 32, j0 = blockIdx.x * 32;   // j0 in {0, 32}
    int tx = threadIdx.x, ty = threadIdx.y;
    const float* Pb = g_P + bh*LL*LL;
    const float* Vb = g_v + bh*LL*HD;
    float c00 = 0.f, c01 = 0.f, c10 = 0.f, c11 = 0.f;
    for (int k0 = 0; k0 < LL; k0 += 32) {
        int t = ty * 16 + tx;
#pragma unroll
        for (int e = 0; e < 4; e++) {
            int idx = t + e*256;
            int rr = idx >> 5, cc = idx & 31;
            int i = i0 + rr, kc = k0 + cc;
            ps[rr][cc] = (i < LL && kc < LL) ? Pb[i*LL + kc] : 0.f;
            int kr = k0 + rr;
            vs[rr][cc] = (kr < LL) ? Vb[kr*HD + j0 + cc] : 0.f;
        }
        __syncthreads();
#pragma unroll
        for (int kk = 0; kk < 32; kk++) {
            float a0 = ps[ty][kk],    a1 = ps[ty+16][kk];
            float b0 = vs[kk][tx],    b1 = vs[kk][tx+16];
            c00 += a0*b0; c01 += a0*b1; c10 += a1*b0; c11 += a1*b1;
        }
        __syncthreads();
    }
    int b = bh / HH, h = bh % HH;
    int i, dd;
    i = i0+ty;    dd = j0+tx;    if (i<LL) g_O[(b*LL+i)*DD + h*HD + dd] = c00;
    i = i0+ty;    dd = j0+tx+16; if (i<LL) g_O[(b*LL+i)*DD + h*HD + dd] = c01;
    i = i0+ty+16; dd = j0+tx;    if (i<LL) g_O[(b*LL+i)*DD + h*HD + dd] = c10;
    i = i0+ty+16; dd = j0+tx+16; if (i<LL) g_O[(b*LL+i)*DD + h*HD + dd] = c11;
}

// ---------------- K9: out = O @ Wo^T ---------------------------------------
// grid (8, 15), block (32,32)
__global__ void out_kernel(const float* __restrict__ Wo, float* __restrict__ out) {
    __shared__ float xs[32][33], ws[32][33];
    int tx = threadIdx.x, ty = threadIdx.y;
    int r  = blockIdx.y * 32 + ty;
    int c0 = blockIdx.x * 32;
    float acc = 0.f;
    for (int k0 = 0; k0 < 256; k0 += 32) {
        xs[ty][tx] = (r < NROW) ? g_O[r*256 + k0 + tx] : 0.f;
        ws[ty][tx] = Wo[(c0 + ty)*256 + k0 + tx];
        __syncthreads();
#pragma unroll
        for (int kk = 0; kk < 32; kk++) acc += xs[ty][kk] * ws[tx][kk];
        __syncthreads();
    }
    if (r < NROW) out[r*256 + c0 + tx] = acc;
}

// ---------------- launcher --------------------------------------------------
extern "C" void kernel_launch(void* const* d_in, const int* in_sizes, int n_in,
                              void* d_out, int out_size) {
    const float* x  = (const float*)d_in[0];
    const float* Wq = (const float*)d_in[1];
    const float* Wk = (const float*)d_in[2];
    const float* Wv = (const float*)d_in[3];
    const float* Wo = (const float*)d_in[4];
    float* out = (float*)d_out;

    dim3 blk32(32, 32), blk16(16, 16);

    qkv_kernel<<<dim3(24, 15), blk32>>>(x, Wq, Wk, Wv);
    s_kernel<<<dim3(8, 8, 8), blk32>>>();
    a_kernel<<<dim3(8, 8, 8), blk16>>>();
    deg_kernel<<<225, 256>>>();
    ahat_kernel<<<(BH*LL*LL + 255) / 256, 256>>>();
    gemm225_kernel<0><<<dim3(8, 8, 8), blk16>>>();
    gemm225_kernel<1><<<dim3(8, 8, 8), blk16>>>();
    softmax_kernel<<<225, 256>>>();
    av_kernel<<<dim3(2, 8, 8), blk16>>>();
    out_kernel<<<dim3(8, 15), blk32>>>(Wo, out);
}

// round 3
// speedup vs baseline: 1.4688x; 1.4688x over previous
#include <cuda_runtime.h>
#include <math.h>

#define BB 2
#define LL 225
#define DD 256
#define HH 4
#define HD 64
#define BH 8
#define NROW 450
#define LP 240

// ---------------- scratch ----------------------------------------------------
__device__ __align__(16) float g_q[BH*LL*HD];
__device__ __align__(16) float g_k[BH*LL*HD];
__device__ __align__(16) float g_v[BH*LL*HD];
__device__ __align__(16) float g_S[BH*LL*LP + 16];
__device__ __align__(16) float g_A[BH*LL*LP + 16];
__device__ __align__(16) float g_T[BH*LL*LP + 16];
__device__ __align__(16) float g_P[BH*LL*LP + 16];
__device__ __align__(16) float g_O[NROW*DD];
__device__ float g_deg[BH*LP];
__device__ float g_dis[BH*LP + 64];

// ---------------- helpers -----------------------------------------------------
__device__ __forceinline__ float4 ld4(const float* p) { return *(const float4*)p; }
__device__ __forceinline__ float4 f4z() { return make_float4(0.f, 0.f, 0.f, 0.f); }

__device__ __forceinline__ unsigned long long pk2(float lo, float hi) {
    unsigned long long r;
    asm("mov.b64 %0,{%1,%2};" : "=l"(r) : "f"(lo), "f"(hi));
    return r;
}
__device__ __forceinline__ void fma2(unsigned long long& d,
                                     unsigned long long a, unsigned long long b) {
    asm("fma.rn.f32x2 %0,%1,%2,%0;" : "+l"(d) : "l"(a), "l"(b));
}
__device__ __forceinline__ float2 up2(unsigned long long v) {
    float2 f;
    asm("mov.b64 {%0,%1},%2;" : "=f"(f.x), "=f"(f.y) : "l"(v));
    return f;
}

// C[4][4] += A(rows x 16, stride AST) * B(16 x cols, stride BST), packed f32x2.
template<int AST, int BST>
__device__ __forceinline__ void inner16(const float* As, const float* Bs,
                                        int ty4, int tx4, unsigned long long acc[4][2]) {
#pragma unroll
    for (int kk = 0; kk < 16; kk++) {
        float4 bv = *(const float4*)(Bs + kk*BST + tx4);
        unsigned long long b01 = pk2(bv.x, bv.y);
        unsigned long long b23 = pk2(bv.z, bv.w);
#pragma unroll
        for (int r = 0; r < 4; r++) {
            float ar = As[(ty4 + r)*AST + kk];
            unsigned long long aa = pk2(ar, ar);
            fma2(acc[r][0], aa, b01);
            fma2(acc[r][1], aa, b23);
        }
    }
}

// ---------------- K1: qkv projections (y = x @ W^T) ---------------------------
// grid (12, 15), block (16, 8). tile 32 rows x 64 cols; cols 0..767 = [Wq|Wk|Wv]
__global__ void qkv_kernel(const float* __restrict__ x,
                           const float* __restrict__ Wq,
                           const float* __restrict__ Wk,
                           const float* __restrict__ Wv) {
    __shared__ __align__(16) float Xs[32][20];
    __shared__ __align__(16) float Ws[16][68];
    int tx = threadIdx.x, ty = threadIdx.y;
    int tid = ty*16 + tx;                 // 0..127
    int m0 = blockIdx.y * 32;
    int c0 = blockIdx.x * 64;
    const float* W = (c0 < 256) ? Wq : (c0 < 512) ? Wk : Wv;
    int cw0 = c0 & 255;
    unsigned long long acc[4][2] = {};
    for (int k0 = 0; k0 < 256; k0 += 16) {
        { int ii = tid >> 2, f = tid & 3;
          int m = m0 + ii;
          float4 v = (m < NROW) ? ld4(x + m*256 + k0 + 4*f) : f4z();
          *(float4*)&Xs[ii][4*f] = v; }
#pragma unroll
        for (int s = 0; s < 2; s++) {
            int idx = tid + 128*s;
            int ll = idx >> 2, g = idx & 3;
            float4 w = ld4(W + (cw0 + ll)*256 + k0 + 4*g);
            Ws[4*g+0][ll] = w.x; Ws[4*g+1][ll] = w.y;
            Ws[4*g+2][ll] = w.z; Ws[4*g+3][ll] = w.w;
        }
        __syncthreads();
        inner16<20, 68>(&Xs[0][0], &Ws[0][0], ty*4, tx*4, acc);
        __syncthreads();
    }
    int which = c0 >> 8, hb = (c0 & 255) >> 6;
    float* dst = (which == 0) ? g_q : (which == 1) ? g_k : g_v;
#pragma unroll
    for (int r = 0; r < 4; r++) {
        int m = m0 + ty*4 + r;
        if (m < NROW) {
            int b = (m >= LL) ? 1 : 0;
            int l = m - b*LL;
            float2 lo = up2(acc[r][0]), hi = up2(acc[r][1]);
            *(float4*)(dst + ((b*HH + hb)*LL + l)*HD + tx*4) =
                make_float4(lo.x, lo.y, hi.x, hi.y);
        }
    }
}

// ---------------- K2: S = q @ k^T per (b,h), also zero g_deg -------------------
// grid (4, 4, 8), block (16,16). tile 64x64, K=64.
__global__ void s_kernel() {
    __shared__ __align__(16) float Qs[64][20];
    __shared__ __align__(16) float Ks[16][68];
    int tx = threadIdx.x, ty = threadIdx.y;
    int tid = ty*16 + tx;                 // 0..255
    int bh = blockIdx.z;
    if (blockIdx.x == 0 && blockIdx.y == 0 && tid < LP) g_deg[bh*LP + tid] = 0.f;
    int i0 = blockIdx.y*64, j0 = blockIdx.x*64;
    const float* qb = g_q + bh*LL*HD;
    const float* kb = g_k + bh*LL*HD;
    unsigned long long acc[4][2] = {};
#pragma unroll
    for (int d0 = 0; d0 < 64; d0 += 16) {
        { int ii = tid >> 2, f = tid & 3;
          int i = i0 + ii;
          float4 v = (i < LL) ? ld4(qb + i*HD + d0 + 4*f) : f4z();
          *(float4*)&Qs[ii][4*f] = v; }
        { int ll = tid >> 2, f = tid & 3;
          int j = j0 + ll;
          float4 v = (j < LL) ? ld4(kb + j*HD + d0 + 4*f) : f4z();
          Ks[4*f+0][ll] = v.x; Ks[4*f+1][ll] = v.y;
          Ks[4*f+2][ll] = v.z; Ks[4*f+3][ll] = v.w; }
        __syncthreads();
        inner16<20, 68>(&Qs[0][0], &Ks[0][0], ty*4, tx*4, acc);
        __syncthreads();
    }
    float* Sb = g_S + bh*LL*LP;
    int jc = j0 + tx*4;
    if (jc < LP) {
#pragma unroll
        for (int r = 0; r < 4; r++) {
            int i = i0 + ty*4 + r;
            if (i < LL) {
                float2 lo = up2(acc[r][0]), hi = up2(acc[r][1]);
                *(float4*)(Sb + i*LP + jc) = make_float4(lo.x, lo.y, hi.x, hi.y);
            }
        }
    }
}

// ---------------- K3: adjacency (symmetric tile pairs) + fused deg -------------
// grid (10, 8), block (16,16,2). A[i,k]=(1/(64*225))*sum_j t, t=S_ij*S_kj if t>6.4
__global__ void a_kernel() {
    __shared__ __align__(16) float Si[2][64][20];
    __shared__ __align__(16) float Sk[2][16][68];
    __shared__ float asA[64][68];
    __shared__ float sdeg[64];
    int tx = threadIdx.x, ty = threadIdx.y, tz = threadIdx.z;
    int tid = ty*16 + tx;
    int p = blockIdx.x, bh = blockIdx.y;
    int ti = (p < 4) ? 0 : (p < 7) ? 1 : (p < 9) ? 2 : 3;
    int tk = (p < 4) ? p : (p < 7) ? p - 3 : (p < 9) ? p - 5 : 3;
    int i0 = ti*64, k0 = tk*64;
    const float* Sb = g_S + bh*LL*LP;
    const float THR = 6.4f;
    float a[4][4] = {};
#pragma unroll 1
    for (int m = 0; m < 8; m++) {
        int j0 = tz*16 + m*32;
        bool jv = (j0 < LP);
        { int ii = tid >> 2, f = tid & 3;
          int i = i0 + ii;
          float4 v = (jv && i < LL) ? ld4(Sb + i*LP + j0 + 4*f) : f4z();
          *(float4*)&Si[tz][ii][4*f] = v; }
        { int ll = tid >> 2, f = tid & 3;
          int k = k0 + ll;
          float4 v = (jv && k < LL) ? ld4(Sb + k*LP + j0 + 4*f) : f4z();
          Sk[tz][4*f+0][ll] = v.x; Sk[tz][4*f+1][ll] = v.y;
          Sk[tz][4*f+2][ll] = v.z; Sk[tz][4*f+3][ll] = v.w; }
        __syncthreads();
#pragma unroll
        for (int jj = 0; jj < 16; jj++) {
            float4 bv = *(const float4*)&Sk[tz][jj][tx*4];
#pragma unroll
            for (int r = 0; r < 4; r++) {
                float ar = Si[tz][ty*4 + r][jj];
                float t0 = ar*bv.x; if (t0 > THR) a[r][0] += t0;
                float t1 = ar*bv.y; if (t1 > THR) a[r][1] += t1;
                float t2 = ar*bv.z; if (t2 > THR) a[r][2] += t2;
                float t3 = ar*bv.w; if (t3 > THR) a[r][3] += t3;
            }
        }
        __syncthreads();
    }
    if (tz == 1) {
#pragma unroll
        for (int r = 0; r < 4; r++)
#pragma unroll
            for (int c = 0; c < 4; c++)
                asA[ty*4 + r][tx*4 + c] = a[r][c];
    }
    if (tz == 0 && tid < 64) sdeg[tid] = 0.f;
    __syncthreads();
    if (tz == 0) {
        const float sc = 1.f / (64.f * 225.f);
        float av[4][4];
#pragma unroll
        for (int r = 0; r < 4; r++)
#pragma unroll
            for (int c = 0; c < 4; c++) {
                int ig = i0 + ty*4 + r, kg = k0 + tx*4 + c;
                float v = (a[r][c] + asA[ty*4 + r][tx*4 + c]) * sc;
                av[r][c] = (ig == kg) ? 0.f : v;
            }
        float* Ab = g_A + bh*LL*LP;
        int kcb = k0 + tx*4;
#pragma unroll
        for (int r = 0; r < 4; r++) {
            int ig = i0 + ty*4 + r;
            if (ig < LL && kcb < LP)
                *(float4*)(Ab + ig*LP + kcb) =
                    make_float4(av[r][0], av[r][1], av[r][2], av[r][3]);
        }
        if (ti != tk) {
            int icb = i0 + ty*4;   // ti<3 here, so icb <= 188 < LP
#pragma unroll
            for (int c = 0; c < 4; c++) {
                int kg = k0 + tx*4 + c;
                if (kg < LL)
                    *(float4*)(Ab + kg*LP + icb) =
                        make_float4(av[0][c], av[1][c], av[2][c], av[3][c]);
            }
        }
        // row sums -> g_deg[i]   (reduce over tx: 16 lanes of a half-warp)
#pragma unroll
        for (int r = 0; r < 4; r++) {
            float rs = av[r][0] + av[r][1] + av[r][2] + av[r][3];
#pragma unroll
            for (int off = 8; off > 0; off >>= 1)
                rs += __shfl_xor_sync(0xffffffffu, rs, off);
            int ig = i0 + ty*4 + r;
            if (tx == 0 && ig < LL) atomicAdd(&g_deg[bh*LP + ig], rs);
        }
        // col sums -> g_deg[k] (mirrored tile contribution)
        if (ti != tk) {
#pragma unroll
            for (int c = 0; c < 4; c++) {
                float cs = av[0][c] + av[1][c] + av[2][c] + av[3][c];
                atomicAdd(&sdeg[tx*4 + c], cs);
            }
        }
    }
    __syncthreads();
    if (tz == 0 && tid < 64 && ti != tk) {
        int kg = k0 + tid;
        if (kg < LL) atomicAdd(&g_deg[bh*LP + kg], sdeg[tid]);
    }
}

// ---------------- K4: dis = rsqrt(max(1+deg,1e-6)) -----------------------------
__global__ void dis_kernel() {
    int t = blockIdx.x*256 + threadIdx.x;
    if (t < BH*LP) g_dis[t] = rsqrtf(fmaxf(1.f + g_deg[t], 1e-6f));
}

// ---------------- K5/K6: 225^3 GEMMs with A_hat built on the fly ----------------
// MODE 0: T = A_hat @ S       : As = (A[i][k]+d_ik)*dis[k], Bs = S,  epi *dis[i]
// MODE 1: P = T @ A_hat / 8   : As = T,  Bs = (A[k][j]+d_kj)*dis[k], epi *dis[j]/8
// (A_hat is symmetric, so A_hat^T == A_hat.)   grid (4,4,8), block (16,16)
template<int MODE>
__global__ void gemm_kernel() {
    __shared__ __align__(16) float As[64][20];
    __shared__ __align__(16) float Bs[16][68];
    int tx = threadIdx.x, ty = threadIdx.y;
    int tid = ty*16 + tx;
    int bh = blockIdx.z;
    int i0 = blockIdx.y*64, j0 = blockIdx.x*64;
    const float* Aop = ((MODE == 0) ? g_A : g_T) + bh*LL*LP;
    const float* Bop = ((MODE == 0) ? g_S : g_A) + bh*LL*LP;
    float*       Cb  = ((MODE == 0) ? g_T : g_P) + bh*LL*LP;
    const float* db = g_dis + bh*LP;
    unsigned long long acc[4][2] = {};
    for (int k0 = 0; k0 < LP; k0 += 16) {
        { int ii = tid >> 2, f = tid & 3;
          int i = i0 + ii;
          float4 v = (i < LL) ? ld4(Aop + i*LP + k0 + 4*f) : f4z();
          if (MODE == 0) {
              float4 dk = ld4(db + k0 + 4*f);
              v.x *= dk.x; v.y *= dk.y; v.z *= dk.z; v.w *= dk.w;
              int dj = i - (k0 + 4*f);
              if (dj == 0) v.x += dk.x; else if (dj == 1) v.y += dk.y;
              else if (dj == 2) v.z += dk.z; else if (dj == 3) v.w += dk.w;
          }
          *(float4*)&As[ii][4*f] = v; }
        { int kk = tid >> 4, j4 = (tid & 15) * 4;
          int k = k0 + kk, j = j0 + j4;
          float4 v = (k < LL && j < LP) ? ld4(Bop + k*LP + j) : f4z();
          if (MODE == 1) {
              float dk = (k < LL) ? db[k] : 0.f;
              v.x *= dk; v.y *= dk; v.z *= dk; v.w *= dk;
              int dj = k - j;
              if (dj == 0) v.x += dk; else if (dj == 1) v.y += dk;
              else if (dj == 2) v.z += dk; else if (dj == 3) v.w += dk;
          }
          *(float4*)&Bs[kk][j4] = v; }
        __syncthreads();
        inner16<20, 68>(&As[0][0], &Bs[0][0], ty*4, tx*4, acc);
        __syncthreads();
    }
    int jc = j0 + tx*4;
    if (jc < LP) {
        float4 sj = make_float4(1.f, 1.f, 1.f, 1.f);
        if (MODE == 1) sj = ld4(db + jc);
#pragma unroll
        for (int r = 0; r < 4; r++) {
            int i = i0 + ty*4 + r;
            if (i < LL) {
                float2 lo = up2(acc[r][0]), hi = up2(acc[r][1]);
                float4 o = make_float4(lo.x, lo.y, hi.x, hi.y);
                if (MODE == 0) {
                    float di = db[i];
                    o.x *= di; o.y *= di; o.z *= di; o.w *= di;
                } else {
                    o.x *= sj.x * 0.125f; o.y *= sj.y * 0.125f;
                    o.z *= sj.z * 0.125f; o.w *= sj.w * 0.125f;
                }
                *(float4*)(Cb + i*LP + jc) = o;
            }
        }
    }
}

// ---------------- K7: row softmax of P in place (warp per row) ------------------
// grid 113, block 512
__global__ void softmax_kernel() {
    int w = threadIdx.x >> 5, lane = threadIdx.x & 31;
    int row = blockIdx.x * 16 + w;
    if (row >= BH*LL) return;
    float* Pr = g_P + row * LP;
    float vals[8];
    float mx = -1e30f;
#pragma unroll
    for (int e = 0; e < 8; e++) {
        int j = lane + e*32;
        vals[e] = (j < LL) ? Pr[j] : -1e30f;
        mx = fmaxf(mx, vals[e]);
    }
#pragma unroll
    for (int off = 16; off > 0; off >>= 1)
        mx = fmaxf(mx, __shfl_xor_sync(0xffffffffu, mx, off));
    float s = 0.f;
#pragma unroll
    for (int e = 0; e < 8; e++) {
        vals[e] = __expf(vals[e] - mx);
        s += vals[e];
    }
#pragma unroll
    for (int off = 16; off > 0; off >>= 1)
        s += __shfl_xor_sync(0xffffffffu, s, off);
    float inv = 1.f / s;
#pragma unroll
    for (int e = 0; e < 8; e++) {
        int j = lane + e*32;
        if (j < LL) Pr[j] = vals[e] * inv;
    }
}

// ---------------- K8: O = attn @ v, merge heads ---------------------------------
// grid (4, 8), block (16,16). tile 64 x 64(=HD)
__global__ void av_kernel() {
    __shared__ __align__(16) float Ps[64][20];
    __shared__ __align__(16) float Vs[16][68];
    int tx = threadIdx.x, ty = threadIdx.y;
    int tid = ty*16 + tx;
    int bh = blockIdx.y;
    int i0 = blockIdx.x*64;
    const float* Pb = g_P + bh*LL*LP;
    const float* Vb = g_v + bh*LL*HD;
    unsigned long long acc[4][2] = {};
    for (int k0 = 0; k0 < LP; k0 += 16) {
        { int ii = tid >> 2, f = tid & 3;
          int i = i0 + ii;
          float4 v = (i < LL) ? ld4(Pb + i*LP + k0 + 4*f) : f4z();
          *(float4*)&Ps[ii][4*f] = v; }
        { int kk = tid >> 4, d4 = (tid & 15) * 4;
          int k = k0 + kk;
          float4 v = (k < LL) ? ld4(Vb + k*HD + d4) : f4z();
          *(float4*)&Vs[kk][d4] = v; }
        __syncthreads();
        inner16<20, 68>(&Ps[0][0], &Vs[0][0], ty*4, tx*4, acc);
        __syncthreads();
    }
    int b = bh >> 2, h = bh & 3;
#pragma unroll
    for (int r = 0; r < 4; r++) {
        int i = i0 + ty*4 + r;
        if (i < LL) {
            float2 lo = up2(acc[r][0]), hi = up2(acc[r][1]);
            *(float4*)(g_O + (b*LL + i)*DD + h*HD + tx*4) =
                make_float4(lo.x, lo.y, hi.x, hi.y);
        }
    }
}

// ---------------- K9: out = O @ Wo^T --------------------------------------------
// grid (4, 8), block (16,16). tile 64x64, K=256
__global__ void out_kernel(const float* __restrict__ Wo, float* __restrict__ out) {
    __shared__ __align__(16) float Os[64][20];
    __shared__ __align__(16) float Ws[16][68];
    int tx = threadIdx.x, ty = threadIdx.y;
    int tid = ty*16 + tx;
    int m0 = blockIdx.y*64, c0 = blockIdx.x*64;
    unsigned long long acc[4][2] = {};
    for (int k0 = 0; k0 < 256; k0 += 16) {
        { int ii = tid >> 2, f = tid & 3;
          int m = m0 + ii;
          float4 v = (m < NROW) ? ld4(g_O + m*256 + k0 + 4*f) : f4z();
          *(float4*)&Os[ii][4*f] = v; }
        { int ll = tid >> 2, f = tid & 3;
          float4 w = ld4(Wo + (c0 + ll)*256 + k0 + 4*f);
          Ws[4*f+0][ll] = w.x; Ws[4*f+1][ll] = w.y;
          Ws[4*f+2][ll] = w.z; Ws[4*f+3][ll] = w.w; }
        __syncthreads();
        inner16<20, 68>(&Os[0][0], &Ws[0][0], ty*4, tx*4, acc);
        __syncthreads();
    }
#pragma unroll
    for (int r = 0; r < 4; r++) {
        int m = m0 + ty*4 + r;
        if (m < NROW) {
            float2 lo = up2(acc[r][0]), hi = up2(acc[r][1]);
            *(float4*)(out + m*256 + c0 + tx*4) =
                make_float4(lo.x, lo.y, hi.x, hi.y);
        }
    }
}

// ---------------- launcher -------------------------------------------------------
extern "C" void kernel_launch(void* const* d_in, const int* in_sizes, int n_in,
                              void* d_out, int out_size) {
    const float* x  = (const float*)d_in[0];
    const float* Wq = (const float*)d_in[1];
    const float* Wk = (const float*)d_in[2];
    const float* Wv = (const float*)d_in[3];
    const float* Wo = (const float*)d_in[4];
    float* out = (float*)d_out;

    dim3 b16(16, 16), b168(16, 8), b162(16, 16, 2);

    qkv_kernel<<<dim3(12, 15), b168>>>(x, Wq, Wk, Wv);
    s_kernel<<<dim3(4, 4, 8), b16>>>();
    a_kernel<<<dim3(10, 8), b162>>>();
    dis_kernel<<<8, 256>>>();
    gemm_kernel<0><<<dim3(4, 4, 8), b16>>>();
    gemm_kernel<1><<<dim3(4, 4, 8), b16>>>();
    softmax_kernel<<<113, 512>>>();
    av_kernel<<<dim3(4, 8), b16>>>();
    out_kernel<<<dim3(4, 8), b16>>>(Wo, out);
}

// round 4
// speedup vs baseline: 1.6510x; 1.1241x over previous
#include <cuda_runtime.h>
#include <math.h>

#define BB 2
#define LL 225
#define DD 256
#define HH 4
#define HD 64
#define BH 8
#define NROW 450
#define LP 240

// ---------------- scratch ----------------------------------------------------
__device__ __align__(16) float g_q[BH*LL*HD];
__device__ __align__(16) float g_k[BH*LL*HD];
__device__ __align__(16) float g_v[BH*LL*HD];
__device__ __align__(16) float g_S[BH*LL*LP + 16];
__device__ __align__(16) float g_A[BH*LL*LP + 16];
__device__ __align__(16) float g_T[BH*LL*LP + 16];
__device__ __align__(16) float g_P[BH*LL*LP + 16];
__device__ __align__(16) float g_O[NROW*DD];
__device__ float g_deg[BH*LP];

// ---------------- helpers -----------------------------------------------------
__device__ __forceinline__ float4 ld4(const float* p) { return *(const float4*)p; }
__device__ __forceinline__ float4 f4z() { return make_float4(0.f, 0.f, 0.f, 0.f); }

__device__ __forceinline__ unsigned long long pk2(float lo, float hi) {
    unsigned long long r;
    asm("mov.b64 %0,{%1,%2};" : "=l"(r) : "f"(lo), "f"(hi));
    return r;
}
__device__ __forceinline__ void fma2(unsigned long long& d,
                                     unsigned long long a, unsigned long long b) {
    asm("fma.rn.f32x2 %0,%1,%2,%0;" : "+l"(d) : "l"(a), "l"(b));
}
__device__ __forceinline__ float2 up2(unsigned long long v) {
    float2 f;
    asm("mov.b64 {%0,%1},%2;" : "=f"(f.x), "=f"(f.y) : "l"(v));
    return f;
}

// C[4][4] += A(.. x16, stride AST) * B(16 x .., stride BST), packed f32x2
template<int AST, int BST>
__device__ __forceinline__ void inner16(const float* As, const float* Bs,
                                        int ty4, int tx4, unsigned long long acc[4][2]) {
#pragma unroll
    for (int kk = 0; kk < 16; kk++) {
        float4 bv = *(const float4*)(Bs + kk*BST + tx4);
        unsigned long long b01 = pk2(bv.x, bv.y);
        unsigned long long b23 = pk2(bv.z, bv.w);
#pragma unroll
        for (int r = 0; r < 4; r++) {
            float ar = As[(ty4 + r)*AST + kk];
            unsigned long long aa = pk2(ar, ar);
            fma2(acc[r][0], aa, b01);
            fma2(acc[r][1], aa, b23);
        }
    }
}

// C[2][4] variant for 32-row tiles
template<int AST, int BST>
__device__ __forceinline__ void inner16_2(const float* As, const float* Bs,
                                          int ty2, int tx4, unsigned long long acc[2][2]) {
#pragma unroll
    for (int kk = 0; kk < 16; kk++) {
        float4 bv = *(const float4*)(Bs + kk*BST + tx4);
        unsigned long long b01 = pk2(bv.x, bv.y);
        unsigned long long b23 = pk2(bv.z, bv.w);
#pragma unroll
        for (int r = 0; r < 2; r++) {
            float ar = As[(ty2 + r)*AST + kk];
            unsigned long long aa = pk2(ar, ar);
            fma2(acc[r][0], aa, b01);
            fma2(acc[r][1], aa, b23);
        }
    }
}

// ---------------- K1: qkv projections (y = x @ W^T) ---------------------------
// grid (12, 15), block (16, 8). tile 32 rows x 64 cols; cols 0..767 = [Wq|Wk|Wv]
__global__ void qkv_kernel(const float* __restrict__ x,
                           const float* __restrict__ Wq,
                           const float* __restrict__ Wk,
                           const float* __restrict__ Wv) {
    __shared__ __align__(16) float Xs[32][20];
    __shared__ __align__(16) float Ws[16][68];
    int tx = threadIdx.x, ty = threadIdx.y;
    int tid = ty*16 + tx;                 // 0..127
    int m0 = blockIdx.y * 32;
    int c0 = blockIdx.x * 64;
    const float* W = (c0 < 256) ? Wq : (c0 < 512) ? Wk : Wv;
    int cw0 = c0 & 255;
    unsigned long long acc[4][2] = {};
    for (int k0 = 0; k0 < 256; k0 += 16) {
        { int ii = tid >> 2, f = tid & 3;
          int m = m0 + ii;
          float4 v = (m < NROW) ? ld4(x + m*256 + k0 + 4*f) : f4z();
          *(float4*)&Xs[ii][4*f] = v; }
#pragma unroll
        for (int s = 0; s < 2; s++) {
            int idx = tid + 128*s;
            int ll = idx >> 2, g = idx & 3;
            float4 w = ld4(W + (cw0 + ll)*256 + k0 + 4*g);
            Ws[4*g+0][ll] = w.x; Ws[4*g+1][ll] = w.y;
            Ws[4*g+2][ll] = w.z; Ws[4*g+3][ll] = w.w;
        }
        __syncthreads();
        inner16<20, 68>(&Xs[0][0], &Ws[0][0], ty*4, tx*4, acc);
        __syncthreads();
    }
    int which = c0 >> 8, hb = (c0 & 255) >> 6;
    float* dst = (which == 0) ? g_q : (which == 1) ? g_k : g_v;
#pragma unroll
    for (int r = 0; r < 4; r++) {
        int m = m0 + ty*4 + r;
        if (m < NROW) {
            int b = (m >= LL) ? 1 : 0;
            int l = m - b*LL;
            float2 lo = up2(acc[r][0]), hi = up2(acc[r][1]);
            *(float4*)(dst + ((b*HH + hb)*LL + l)*HD + tx*4) =
                make_float4(lo.x, lo.y, hi.x, hi.y);
        }
    }
}

// ---------------- K2: S = q @ k^T per (b,h), also zero g_deg -------------------
// grid (4, 4, 8), block (16,16). tile 64x64, K=64.
__global__ void s_kernel() {
    __shared__ __align__(16) float Qs[64][20];
    __shared__ __align__(16) float Ks[16][68];
    int tx = threadIdx.x, ty = threadIdx.y;
    int tid = ty*16 + tx;
    int bh = blockIdx.z;
    if (blockIdx.x == 0 && blockIdx.y == 0 && tid < LP) g_deg[bh*LP + tid] = 0.f;
    int i0 = blockIdx.y*64, j0 = blockIdx.x*64;
    const float* qb = g_q + bh*LL*HD;
    const float* kb = g_k + bh*LL*HD;
    unsigned long long acc[4][2] = {};
#pragma unroll
    for (int d0 = 0; d0 < 64; d0 += 16) {
        { int ii = tid >> 2, f = tid & 3;
          int i = i0 + ii;
          float4 v = (i < LL) ? ld4(qb + i*HD + d0 + 4*f) : f4z();
          *(float4*)&Qs[ii][4*f] = v; }
        { int ll = tid >> 2, f = tid & 3;
          int j = j0 + ll;
          float4 v = (j < LL) ? ld4(kb + j*HD + d0 + 4*f) : f4z();
          Ks[4*f+0][ll] = v.x; Ks[4*f+1][ll] = v.y;
          Ks[4*f+2][ll] = v.z; Ks[4*f+3][ll] = v.w; }
        __syncthreads();
        inner16<20, 68>(&Qs[0][0], &Ks[0][0], ty*4, tx*4, acc);
        __syncthreads();
    }
    float* Sb = g_S + bh*LL*LP;
    int jc = j0 + tx*4;
    if (jc < LP) {
#pragma unroll
        for (int r = 0; r < 4; r++) {
            int i = i0 + ty*4 + r;
            if (i < LL) {
                float2 lo = up2(acc[r][0]), hi = up2(acc[r][1]);
                *(float4*)(Sb + i*LP + jc) = make_float4(lo.x, lo.y, hi.x, hi.y);
            }
        }
    }
}

// ---------------- K3: adjacency, 32x32 symmetric tile pairs + fused deg --------
// grid (36, 8), block (16,16). 36 pairs of 32-wide tile blocks (ti <= tk).
__global__ void a_kernel() {
    __shared__ __align__(16) float Si[32][20];
    __shared__ __align__(8)  float Sk[16][36];
    __shared__ float scol[32];
    int tx = threadIdx.x, ty = threadIdx.y;
    int tid = ty*16 + tx;
    int p = blockIdx.x, bh = blockIdx.y;
    int ti = 0, rem = p;
    while (rem >= 8 - ti) { rem -= 8 - ti; ti++; }
    int tk = ti + rem;
    int i0 = ti*32, k0 = tk*32;
    const float* Sb = g_S + bh*LL*LP;
    const float THR = 0.1f * 64.f;
    float a00 = 0.f, a01 = 0.f, a10 = 0.f, a11 = 0.f;
    if (tid < 32) scol[tid] = 0.f;
    for (int j0 = 0; j0 < LP; j0 += 16) {
        if (tid < 128) {
            int ii = tid >> 2, f = tid & 3;
            int i = i0 + ii;
            float4 v = (i < LL) ? ld4(Sb + i*LP + j0 + 4*f) : f4z();
            *(float4*)&Si[ii][4*f] = v;
        } else {
            int idx = tid - 128;
            int ll = idx >> 2, f = idx & 3;
            int k = k0 + ll;
            float4 v = (k < LL) ? ld4(Sb + k*LP + j0 + 4*f) : f4z();
            Sk[4*f+0][ll] = v.x; Sk[4*f+1][ll] = v.y;
            Sk[4*f+2][ll] = v.z; Sk[4*f+3][ll] = v.w;
        }
        __syncthreads();
#pragma unroll
        for (int jj = 0; jj < 16; jj++) {
            float2 bv = *(const float2*)&Sk[jj][tx*2];
            float a0 = Si[ty*2][jj], a1 = Si[ty*2+1][jj];
            float t;
            t = a0*bv.x; if (t > THR) a00 += t;
            t = a0*bv.y; if (t > THR) a01 += t;
            t = a1*bv.x; if (t > THR) a10 += t;
            t = a1*bv.y; if (t > THR) a11 += t;
        }
        __syncthreads();
    }
    const float sc = 1.f / (64.f * 225.f);
    int ig0 = i0 + ty*2, kg0 = k0 + tx*2;
    float av[2][2] = {{a00*sc, a01*sc}, {a10*sc, a11*sc}};
#pragma unroll
    for (int r = 0; r < 2; r++)
#pragma unroll
        for (int c = 0; c < 2; c++)
            if (ig0 + r == kg0 + c) av[r][c] = 0.f;
    float* Ab = g_A + bh*LL*LP;
#pragma unroll
    for (int r = 0; r < 2; r++) {
        int ig = ig0 + r;
        if (ig < LL) {
#pragma unroll
            for (int c = 0; c < 2; c++) {
                int kg = kg0 + c;
                if (kg < LP) Ab[ig*LP + kg] = av[r][c];
            }
        }
    }
    if (ti != tk) {
#pragma unroll
        for (int c = 0; c < 2; c++) {
            int kg = kg0 + c;
            if (kg < LL) {
#pragma unroll
                for (int r = 0; r < 2; r++) {
                    int ig = ig0 + r;
                    if (ig < LP) Ab[kg*LP + ig] = av[r][c];
                }
            }
        }
    }
    // deg rows (reduce across tx half-warp)
#pragma unroll
    for (int r = 0; r < 2; r++) {
        float rs = av[r][0] + av[r][1];
#pragma unroll
        for (int off = 8; off > 0; off >>= 1)
            rs += __shfl_xor_sync(0xffffffffu, rs, off);
        int ig = ig0 + r;
        if (tx == 0 && ig < LL) atomicAdd(&g_deg[bh*LP + ig], rs);
    }
    // deg cols (mirror contribution)
    if (ti != tk) {
#pragma unroll
        for (int c = 0; c < 2; c++) {
            float cs = av[0][c] + av[1][c];
            atomicAdd(&scol[tx*2 + c], cs);
        }
        __syncthreads();
        if (tid < 32) {
            int kg = k0 + tid;
            if (kg < LL) atomicAdd(&g_deg[bh*LP + kg], scol[tid]);
        }
    }
}

// ---------------- K4/K5: 225^3 GEMMs, A_hat + dis built on the fly -------------
// MODE 0: T = A_hat @ S        MODE 1: P = T @ A_hat / 8  (A_hat symmetric)
// grid (4,4,8), block (16,16)
template<int MODE>
__global__ void gemm_kernel() {
    __shared__ __align__(16) float As[64][20];
    __shared__ __align__(16) float Bs[16][68];
    __shared__ __align__(16) float sdis[LP];
    int tx = threadIdx.x, ty = threadIdx.y;
    int tid = ty*16 + tx;
    int bh = blockIdx.z;
    int i0 = blockIdx.y*64, j0 = blockIdx.x*64;
    if (tid < LP) sdis[tid] = rsqrtf(fmaxf(1.f + g_deg[bh*LP + tid], 1e-6f));
    __syncthreads();
    const float* Aop = ((MODE == 0) ? g_A : g_T) + bh*LL*LP;
    const float* Bop = ((MODE == 0) ? g_S : g_A) + bh*LL*LP;
    float*       Cb  = ((MODE == 0) ? g_T : g_P) + bh*LL*LP;
    unsigned long long acc[4][2] = {};
    for (int k0 = 0; k0 < LP; k0 += 16) {
        { int ii = tid >> 2, f = tid & 3;
          int i = i0 + ii;
          float4 v = (i < LL) ? ld4(Aop + i*LP + k0 + 4*f) : f4z();
          if (MODE == 0) {
              float4 dk = *(const float4*)&sdis[k0 + 4*f];
              v.x *= dk.x; v.y *= dk.y; v.z *= dk.z; v.w *= dk.w;
              int dj = i - (k0 + 4*f);
              if (dj == 0) v.x += dk.x; else if (dj == 1) v.y += dk.y;
              else if (dj == 2) v.z += dk.z; else if (dj == 3) v.w += dk.w;
          }
          *(float4*)&As[ii][4*f] = v; }
        { int kk = tid >> 4, j4 = (tid & 15) * 4;
          int k = k0 + kk, j = j0 + j4;
          float4 v = (k < LL && j < LP) ? ld4(Bop + k*LP + j) : f4z();
          if (MODE == 1) {
              float dk = (k < LL) ? sdis[k] : 0.f;
              v.x *= dk; v.y *= dk; v.z *= dk; v.w *= dk;
              int dj = k - j;
              if (dj == 0) v.x += dk; else if (dj == 1) v.y += dk;
              else if (dj == 2) v.z += dk; else if (dj == 3) v.w += dk;
          }
          *(float4*)&Bs[kk][j4] = v; }
        __syncthreads();
        inner16<20, 68>(&As[0][0], &Bs[0][0], ty*4, tx*4, acc);
        __syncthreads();
    }
    int jc = j0 + tx*4;
    if (jc < LP) {
        float4 sj = make_float4(1.f, 1.f, 1.f, 1.f);
        if (MODE == 1) sj = *(const float4*)&sdis[jc];
#pragma unroll
        for (int r = 0; r < 4; r++) {
            int i = i0 + ty*4 + r;
            if (i < LL) {
                float2 lo = up2(acc[r][0]), hi = up2(acc[r][1]);
                float4 o = make_float4(lo.x, lo.y, hi.x, hi.y);
                if (MODE == 0) {
                    float di = sdis[i];
                    o.x *= di; o.y *= di; o.z *= di; o.w *= di;
                } else {
                    o.x *= sj.x * 0.125f; o.y *= sj.y * 0.125f;
                    o.z *= sj.z * 0.125f; o.w *= sj.w * 0.125f;
                }
                *(float4*)(Cb + i*LP + jc) = o;
            }
        }
    }
}

// ---------------- K6: fused softmax + O = attn @ v ------------------------------
// grid (8, 8), block (16,16). 32-row tiles, 64 output cols (= HD).
__global__ void av_kernel() {
    __shared__ __align__(16) float Ps[32][20];
    __shared__ __align__(16) float Vs[16][68];
    __shared__ float smx[32], sinv[32];
    int tx = threadIdx.x, ty = threadIdx.y;
    int tid = ty*16 + tx;
    int bh = blockIdx.y;
    int i0 = blockIdx.x*32;
    const float* Pb = g_P + bh*LL*LP;
    const float* Vb = g_v + bh*LL*HD;
    // --- row stats: max + sum(exp) per row ---
    {
        int w = tid >> 5, lane = tid & 31;
#pragma unroll
        for (int rr = 0; rr < 4; rr++) {
            int row = w*4 + rr;
            int i = i0 + row;
            if (i < LL) {
                const float* Pr = Pb + i*LP;
                float vb[8];
                float m = -1e30f;
#pragma unroll
                for (int e = 0; e < 8; e++) {
                    int j = lane + 32*e;
                    float v = (j < LL) ? Pr[j] : -1e30f;
                    vb[e] = v;
                    m = fmaxf(m, v);
                }
#pragma unroll
                for (int off = 16; off > 0; off >>= 1)
                    m = fmaxf(m, __shfl_xor_sync(0xffffffffu, m, off));
                float s = 0.f;
#pragma unroll
                for (int e = 0; e < 8; e++) s += __expf(vb[e] - m);
#pragma unroll
                for (int off = 16; off > 0; off >>= 1)
                    s += __shfl_xor_sync(0xffffffffu, s, off);
                if (lane == 0) { smx[row] = m; sinv[row] = 1.f / s; }
            }
        }
    }
    __syncthreads();
    unsigned long long acc[2][2] = {};
    for (int k0 = 0; k0 < LP; k0 += 16) {
        if (tid < 128) {
            int ii = tid >> 2, f = tid & 3;
            int i = i0 + ii;
            float4 v;
            if (i < LL) {
                v = ld4(Pb + i*LP + k0 + 4*f);
                float m = smx[ii], inv = sinv[ii];
                int kb = k0 + 4*f;
                v.x = (kb + 0 < LL) ? __expf(v.x - m)*inv : 0.f;
                v.y = (kb + 1 < LL) ? __expf(v.y - m)*inv : 0.f;
                v.z = (kb + 2 < LL) ? __expf(v.z - m)*inv : 0.f;
                v.w = (kb + 3 < LL) ? __expf(v.w - m)*inv : 0.f;
            } else v = f4z();
            *(float4*)&Ps[ii][4*f] = v;
        } else {
#pragma unroll
            for (int s2 = 0; s2 < 2; s2++) {
                int idx = (tid - 128) + 128*s2;
                int kk = idx >> 4, d4 = (idx & 15)*4;
                int k = k0 + kk;
                float4 v = (k < LL) ? ld4(Vb + k*HD + d4) : f4z();
                *(float4*)&Vs[kk][d4] = v;
            }
        }
        __syncthreads();
        inner16_2<20, 68>(&Ps[0][0], &Vs[0][0], ty*2, tx*4, acc);
        __syncthreads();
    }
    int b = bh >> 2, h = bh & 3;
#pragma unroll
    for (int r = 0; r < 2; r++) {
        int i = i0 + ty*2 + r;
        if (i < LL) {
            float2 lo = up2(acc[r][0]), hi = up2(acc[r][1]);
            *(float4*)(g_O + (b*LL + i)*DD + h*HD + tx*4) =
                make_float4(lo.x, lo.y, hi.x, hi.y);
        }
    }
}

// ---------------- K7: out = O @ Wo^T ---------------------------------------------
// grid (4, 15), block (16,16). 32-row x 64-col tiles, K=256.
__global__ void out_kernel(const float* __restrict__ Wo, float* __restrict__ out) {
    __shared__ __align__(16) float Os[32][20];
    __shared__ __align__(16) float Ws[16][68];
    int tx = threadIdx.x, ty = threadIdx.y;
    int tid = ty*16 + tx;
    int m0 = blockIdx.y*32, c0 = blockIdx.x*64;
    unsigned long long acc[2][2] = {};
    for (int k0 = 0; k0 < 256; k0 += 16) {
        if (tid < 128) {
            int ii = tid >> 2, f = tid & 3;
            int m = m0 + ii;
            float4 v = (m < NROW) ? ld4(g_O + m*256 + k0 + 4*f) : f4z();
            *(float4*)&Os[ii][4*f] = v;
        } else {
#pragma unroll
            for (int s2 = 0; s2 < 2; s2++) {
                int idx = (tid - 128) + 128*s2;
                int ll = idx >> 2, f = idx & 3;
                float4 w = ld4(Wo + (c0 + ll)*256 + k0 + 4*f);
                Ws[4*f+0][ll] = w.x; Ws[4*f+1][ll] = w.y;
                Ws[4*f+2][ll] = w.z; Ws[4*f+3][ll] = w.w;
            }
        }
        __syncthreads();
        inner16_2<20, 68>(&Os[0][0], &Ws[0][0], ty*2, tx*4, acc);
        __syncthreads();
    }
#pragma unroll
    for (int r = 0; r < 2; r++) {
        int m = m0 + ty*2 + r;
        if (m < NROW) {
            float2 lo = up2(acc[r][0]), hi = up2(acc[r][1]);
            *(float4*)(out + m*256 + c0 + tx*4) =
                make_float4(lo.x, lo.y, hi.x, hi.y);
        }
    }
}

// ---------------- launcher --------------------------------------------------------
extern "C" void kernel_launch(void* const* d_in, const int* in_sizes, int n_in,
                              void* d_out, int out_size) {
    const float* x  = (const float*)d_in[0];
    const float* Wq = (const float*)d_in[1];
    const float* Wk = (const float*)d_in[2];
    const float* Wv = (const float*)d_in[3];
    const float* Wo = (const float*)d_in[4];
    float* out = (float*)d_out;

    dim3 b16(16, 16), b168(16, 8);

    qkv_kernel<<<dim3(12, 15), b168>>>(x, Wq, Wk, Wv);
    s_kernel<<<dim3(4, 4, 8), b16>>>();
    a_kernel<<<dim3(36, 8), b16>>>();
    gemm_kernel<0><<<dim3(4, 4, 8), b16>>>();
    gemm_kernel<1><<<dim3(4, 4, 8), b16>>>();
    av_kernel<<<dim3(8, 8), b16>>>();
    out_kernel<<<dim3(4, 15), b16>>>(Wo, out);
}